// round 1
// baseline (speedup 1.0000x reference)
#include <cuda_runtime.h>
#include <cstdint>

// ---------------------------------------------------------------------------
// SpanRepresentationLayer on GB300
//
// Decomposition:
//   P[b,s, j] = sum_c X[b,s,c] * WT[c, j],  j = half*T*H + t*H + h  (GEMM, tf32)
//   out[b, n*T+t, h] = P[b,start(n), 0,t,h] + P[b,end(n), 1,t,h] + bias[t,h]
//
// Kernels: prep_x / prep_w (tf32-round + permute to GEMM-ready swizzled layout),
//          build_spans, gemm_tf32 (mma.sync m16n8k8 tf32), epilogue (gather-add).
// ---------------------------------------------------------------------------

#define BATCH   8
#define SEQ     1024
#define HID     256
#define NTYPES  4
#define DEF_SPAN 12

#define GM (BATCH*SEQ)        // 8192 rows
#define GN (2*NTYPES*HID)     // 2048 cols (half,t,h)
#define GK HID                // 256

#define BM 128
#define BN 128
#define BK 16

// Static device scratch (no allocations allowed in kernel_launch)
__device__ float g_XP[GM*GK];                 // 8 MB, permuted/swizzled, tf32-rounded
__device__ float g_WP[GN*GK];                 // 2 MB, permuted/swizzled, tf32-rounded
__device__ float g_Y[(size_t)GM*GN];          // 64 MB GEMM output P
__device__ int   g_sstart[16384];
__device__ int   g_send[16384];

// ---------------------------------------------------------------------------
// helpers
// ---------------------------------------------------------------------------
__device__ __forceinline__ float tf32_rna(float v){
    uint32_t u;
    asm("cvt.rna.tf32.f32 %0, %1;" : "=r"(u) : "f"(v));
    return __uint_as_float(u);
}

// permuted index within a 128-wide tile row, with XOR swizzle on 16B chunks.
// lidx in [0,128): f = (lidx%8)*16 + lidx/8 ; chunk = f/4 ; swizzle chunk ^= (k & 15)
__device__ __forceinline__ int swz_idx(int lidx, int k){
    int f = ((lidx & 7) << 4) | (lidx >> 3);
    int chunk = f >> 2;
    return ((chunk ^ (k & 15)) << 2) | (f & 3);
}

__device__ __forceinline__ void cp16(float* dst, const float* src){
    uint32_t d = (uint32_t)__cvta_generic_to_shared(dst);
    asm volatile("cp.async.cg.shared.global [%0], [%1], 16;" :: "r"(d), "l"(src));
}

__device__ __forceinline__ void mma_tf32(float* d, const uint32_t* a, uint32_t b0, uint32_t b1){
    asm volatile(
        "mma.sync.aligned.m16n8k8.row.col.f32.tf32.tf32.f32 "
        "{%0,%1,%2,%3}, {%4,%5,%6,%7}, {%8,%9}, {%0,%1,%2,%3};"
        : "+f"(d[0]), "+f"(d[1]), "+f"(d[2]), "+f"(d[3])
        : "r"(a[0]), "r"(a[1]), "r"(a[2]), "r"(a[3]), "r"(b0), "r"(b1));
}

// ---------------------------------------------------------------------------
// prep kernels: tf32-round + permute into per-128-row-tile GEMM-ready layout
// layout: buf[tile*32768 + k*128 + swz_idx(local_row, k)]
// ---------------------------------------------------------------------------
__global__ void prep_x(const float* __restrict__ X){
    int id = blockIdx.x * blockDim.x + threadIdx.x;
    if (id >= GM*GK) return;
    int m = id >> 8, k = id & 255;                // X row-major [m][k]
    float v = tf32_rna(X[id]);
    g_XP[((m >> 7) << 15) + k*128 + swz_idx(m & 127, k)] = v;
}

__global__ void prep_w(const float* __restrict__ W){
    int id = blockIdx.x * blockDim.x + threadIdx.x;
    if (id >= GN*GK) return;
    int n = id >> 8, k = id & 255;                // logical WT col n, row k
    int half = n >> 10, t = (n >> 8) & 3, h = n & 255;
    // W layout (T,H,2H): W[t][h][half*H + k]
    float v = tf32_rna(W[t*(HID*2*HID) + h*(2*HID) + half*HID + k]);
    g_WP[((n >> 7) << 15) + k*128 + swz_idx(n & 127, k)] = v;
}

// ---------------------------------------------------------------------------
// span table: spans ordered s-major, e = s..min(s+m,S)-1
// ---------------------------------------------------------------------------
__global__ void build_spans(const int* mptr){
    int s = blockIdx.x * blockDim.x + threadIdx.x;
    if (s >= SEQ) return;
    int m = DEF_SPAN;
    if (mptr){
        int raw = mptr[0];
        if (raw >= 1 && raw <= SEQ) m = raw;
        else {
            float f = __int_as_float(raw);
            if (f >= 1.0f && f <= (float)SEQ) m = (int)f;
        }
    }
    int cnt = min(m, SEQ - s);
    int s0 = SEQ - m;                      // last s with full m spans
    long long off;
    if (s <= s0) off = (long long)s * m;
    else {
        int u = s - (s0 + 1);
        off = (long long)(s0 + 1) * m + (long long)u * (m - 1) - (long long)u * (u - 1) / 2;
    }
    for (int i = 0; i < cnt; i++){
        long long o = off + i;
        if (o < 16384){ g_sstart[o] = s; g_send[o] = s + i; }
    }
}

// ---------------------------------------------------------------------------
// GEMM: Y[8192 x 2048] = XP @ WP, tf32 mma.sync, 128x128x16 tiles, 2-stage
// ---------------------------------------------------------------------------
__global__ __launch_bounds__(256) void gemm_tf32(){
    __shared__ __align__(16) float sA[2][BK*BM];
    __shared__ __align__(16) float sB[2][BK*BN];

    const int tid    = threadIdx.x;
    const int lane   = tid & 31;
    const int wid    = tid >> 5;
    const int warp_m = wid & 3;            // 0..3  -> 32 rows each
    const int warp_n = wid >> 2;           // 0..1  -> 64 cols each

    const float* gA = g_XP + ((size_t)blockIdx.y << 15);
    const float* gB = g_WP + ((size_t)blockIdx.x << 15);

    float acc[2][8][4];
    #pragma unroll
    for (int i = 0; i < 2; i++)
        #pragma unroll
        for (int j = 0; j < 8; j++)
            #pragma unroll
            for (int l = 0; l < 4; l++) acc[i][j][l] = 0.f;

    // prologue: load k-tile 0 into buffer 0
    {
        #pragma unroll
        for (int i = 0; i < 2; i++){
            int e = i*256 + tid;           // 16B units, 512 per array per tile
            int kl = e >> 5, p = e & 31;
            cp16(&sA[0][kl*BM + p*4], gA + kl*128 + p*4);
            cp16(&sB[0][kl*BN + p*4], gB + kl*128 + p*4);
        }
        asm volatile("cp.async.commit_group;");
    }

    const int r = lane >> 2, c = lane & 3;
    const int chA = (r << 2) | warp_m;             // 0..31
    const int chB = (r << 2) | (warp_n << 1);      // 0..30

    for (int kt = 0; kt < GK/BK; kt++){
        int bf = kt & 1;
        if (kt < GK/BK - 1){
            const float* gAk = gA + (kt + 1) * (BK*128);
            const float* gBk = gB + (kt + 1) * (BK*128);
            float* dA = sA[bf ^ 1];
            float* dB = sB[bf ^ 1];
            #pragma unroll
            for (int i = 0; i < 2; i++){
                int e = i*256 + tid;
                int kl = e >> 5, p = e & 31;
                cp16(dA + kl*BM + p*4, gAk + kl*128 + p*4);
                cp16(dB + kl*BN + p*4, gBk + kl*128 + p*4);
            }
            asm volatile("cp.async.commit_group;");
            asm volatile("cp.async.wait_group 1;");
        } else {
            asm volatile("cp.async.wait_group 0;");
        }
        __syncthreads();

        const float* A  = sA[bf];
        const float* Bs = sB[bf];

        #pragma unroll
        for (int ks = 0; ks < BK; ks += 8){
            int ka = ks + c;
            float4 av0  = *(const float4*)(A  + ka    *BM + ((chA     ^ ( ka    & 15)) << 2));
            float4 av1  = *(const float4*)(A  + (ka+4)*BM + ((chA     ^ ((ka+4) & 15)) << 2));
            float4 bv00 = *(const float4*)(Bs + ka    *BN + ((chB     ^ ( ka    & 15)) << 2));
            float4 bv01 = *(const float4*)(Bs + ka    *BN + (((chB+1) ^ ( ka    & 15)) << 2));
            float4 bv10 = *(const float4*)(Bs + (ka+4)*BN + ((chB     ^ ((ka+4) & 15)) << 2));
            float4 bv11 = *(const float4*)(Bs + (ka+4)*BN + (((chB+1) ^ ((ka+4) & 15)) << 2));

            uint32_t a0[4] = {__float_as_uint(av0.x), __float_as_uint(av0.y),
                              __float_as_uint(av1.x), __float_as_uint(av1.y)};
            uint32_t a1[4] = {__float_as_uint(av0.z), __float_as_uint(av0.w),
                              __float_as_uint(av1.z), __float_as_uint(av1.w)};
            uint32_t b0[8] = {__float_as_uint(bv00.x), __float_as_uint(bv00.y),
                              __float_as_uint(bv00.z), __float_as_uint(bv00.w),
                              __float_as_uint(bv01.x), __float_as_uint(bv01.y),
                              __float_as_uint(bv01.z), __float_as_uint(bv01.w)};
            uint32_t b1[8] = {__float_as_uint(bv10.x), __float_as_uint(bv10.y),
                              __float_as_uint(bv10.z), __float_as_uint(bv10.w),
                              __float_as_uint(bv11.x), __float_as_uint(bv11.y),
                              __float_as_uint(bv11.z), __float_as_uint(bv11.w)};
            #pragma unroll
            for (int q = 0; q < 8; q++){
                mma_tf32(acc[0][q], a0, b0[q], b1[q]);
                mma_tf32(acc[1][q], a1, b0[q], b1[q]);
            }
        }
        __syncthreads();
    }

    // epilogue: write fp32 accumulators to g_Y
    const int m0 = blockIdx.y*BM + warp_m*32;
    const int n0 = blockIdx.x*BN + warp_n*64;
    #pragma unroll
    for (int mt = 0; mt < 2; mt++){
        #pragma unroll
        for (int q = 0; q < 8; q++){
            int row = m0 + mt*16 + r;
            int col = n0 + q*8 + c*2;
            *(float2*)&g_Y[(size_t)row    *GN + col] = make_float2(acc[mt][q][0], acc[mt][q][1]);
            *(float2*)&g_Y[(size_t)(row+8)*GN + col] = make_float2(acc[mt][q][2], acc[mt][q][3]);
        }
    }
}

// ---------------------------------------------------------------------------
// epilogue: out[b, n*T + t, h] = P1[b,start,t,h] + P2[b,end,t,h] + bias[t,h]
// block = (8 spans) x (b), 256 threads: t_type = tid/64, float4 lane = tid%64
// ---------------------------------------------------------------------------
__global__ __launch_bounds__(256) void epilogue(const float* __restrict__ bias,
                                                float* __restrict__ out, int N){
    const int b   = blockIdx.y;
    const int tid = threadIdx.x;
    const int tt  = tid >> 6;    // type 0..3
    const int v   = tid & 63;    // float4 index within H=256

    const float4 bb = ((const float4*)bias)[tt*64 + v];
    const int n0 = blockIdx.x * 8;

    for (int i = 0; i < 8; i++){
        int n = n0 + i;
        if (n >= N) break;
        int s = g_sstart[n];
        int e = g_send[n];
        const float4* p1 = (const float4*)&g_Y[((size_t)(b*SEQ + s))*GN + tt*HID];
        const float4* p2 = (const float4*)&g_Y[((size_t)(b*SEQ + e))*GN + NTYPES*HID + tt*HID];
        float4 r1 = p1[v];
        float4 r2 = p2[v];
        float4 o = make_float4(r1.x + r2.x + bb.x,
                               r1.y + r2.y + bb.y,
                               r1.z + r2.z + bb.z,
                               r1.w + r2.w + bb.w);
        ((float4*)out)[(((size_t)b*N + n)*NTYPES + tt)*64 + v] = o;
    }
}

// ---------------------------------------------------------------------------
// launch
// ---------------------------------------------------------------------------
extern "C" void kernel_launch(void* const* d_in, const int* in_sizes, int n_in,
                              void* d_out, int out_size){
    const float* X    = (const float*)d_in[0];
    const float* W    = (const float*)d_in[1];
    const float* bias = (const float*)d_in[2];
    const int*   mptr = (n_in > 3) ? (const int*)d_in[3] : nullptr;

    int N = out_size / (BATCH * NTYPES * HID);   // number of spans (12222)

    prep_x<<<(GM*GK)/256, 256>>>(X);
    prep_w<<<(GN*GK)/256, 256>>>(W);
    build_spans<<<(SEQ + 255)/256, 256>>>(mptr);

    dim3 gg(GN/BN, GM/BM);
    gemm_tf32<<<gg, 256>>>();

    dim3 ge((N + 7)/8, BATCH);
    epilogue<<<ge, 256>>>(bias, (float*)d_out, N);
}